// round 1
// baseline (speedup 1.0000x reference)
#include <cuda_runtime.h>

#define MN 100000
#define NE 1600000
#define NG 128
#define FD 128
#define NC 64

// ---------------- device scratch (no runtime allocation allowed) ----------------
__device__ float d_h[2][(size_t)MN * FD];     // projected node features per branch
__device__ int   d_degout[2][MN];
__device__ int   d_cursor[2][MN];             // dst histogram -> row offsets -> scatter cursors
__device__ int   d_rowptr[2][MN + 1];
__device__ int   d_csrsrc[2][NE];
__device__ float d_hg[2][NG * FD];            // graph pools
__device__ int   d_gcnt[2][NG];

__device__ __forceinline__ float f2tf32(float x) {
    unsigned u;
    asm("cvt.rna.tf32.f32 %0, %1;" : "=r"(u) : "f"(x));
    return __uint_as_float(u);
}

// ---------------- K0: zero scratch ----------------
__global__ void k_zero() {
    int i = blockIdx.x * blockDim.x + threadIdx.x;
    if (i < MN) {
        d_degout[0][i] = 0; d_degout[1][i] = 0;
        d_cursor[0][i] = 0; d_cursor[1][i] = 0;
    }
    if (i < NG * FD) { d_hg[0][i] = 0.f; d_hg[1][i] = 0.f; }
    if (i < NG) { d_gcnt[0][i] = 0; d_gcnt[1][i] = 0; }
}

// ---------------- K1: degree histograms ----------------
__global__ void k_hist(const int* __restrict__ s1, const int* __restrict__ d1,
                       const int* __restrict__ s2, const int* __restrict__ d2) {
    int br = blockIdx.y;
    const int* src = br ? s2 : s1;
    const int* dst = br ? d2 : d1;
    int e = blockIdx.x * blockDim.x + threadIdx.x;
    if (e < NE) {
        atomicAdd(&d_degout[br][src[e]], 1);
        atomicAdd(&d_cursor[br][dst[e]], 1);   // in-degree histogram
    }
}

// ---------------- K1b: per-graph node counts ----------------
__global__ void k_gcnt(const int* __restrict__ g1, const int* __restrict__ g2) {
    int br = blockIdx.y;
    const int* gid = br ? g2 : g1;
    int i = blockIdx.x * blockDim.x + threadIdx.x;
    if (i < MN) atomicAdd(&d_gcnt[br][gid[i]], 1);
}

// ---------------- K2: exclusive scan of in-degree histogram (1 CTA per branch) ----------------
__global__ void k_scan() {
    int br = blockIdx.x;
    int* hist = d_cursor[br];
    int* rp = d_rowptr[br];
    __shared__ int wsums[32];
    __shared__ int s_total;
    int tid = threadIdx.x, lane = tid & 31, wid = tid >> 5;
    int carry = 0;
    const int NCH = (MN + 1023) / 1024;
    for (int ch = 0; ch < NCH; ch++) {
        int i = ch * 1024 + tid;
        int v = (i < MN) ? hist[i] : 0;
        int inc = v;
#pragma unroll
        for (int o = 1; o < 32; o <<= 1) {
            int t = __shfl_up_sync(0xffffffffu, inc, o);
            if (lane >= o) inc += t;
        }
        if (lane == 31) wsums[wid] = inc;
        __syncthreads();
        if (wid == 0) {
            int s = wsums[lane];
            int si = s;
#pragma unroll
            for (int o = 1; o < 32; o <<= 1) {
                int t = __shfl_up_sync(0xffffffffu, si, o);
                if (lane >= o) si += t;
            }
            wsums[lane] = si - s;      // exclusive per-warp offsets
            if (lane == 31) s_total = si;
        }
        __syncthreads();
        int excl = carry + wsums[wid] + inc - v;
        if (i < MN) { rp[i] = excl; hist[i] = excl; }  // hist becomes scatter cursor
        carry += s_total;
        __syncthreads();
    }
    if (tid == 0) rp[MN] = carry;
}

// ---------------- K3: scatter edges into dst-CSR ----------------
__global__ void k_scatter(const int* __restrict__ s1, const int* __restrict__ d1,
                          const int* __restrict__ s2, const int* __restrict__ d2) {
    int br = blockIdx.y;
    const int* src = br ? s2 : s1;
    const int* dst = br ? d2 : d1;
    int e = blockIdx.x * blockDim.x + threadIdx.x;
    if (e < NE) {
        int pos = atomicAdd(&d_cursor[br][dst[e]], 1);
        d_csrsrc[br][pos] = src[e];
    }
}

// ---------------- K4: h = diag(degout^-1/2) * feat @ W  (tf32 mma) ----------------
__global__ void __launch_bounds__(256) k_gemm(const float* __restrict__ f1,
                                              const float* __restrict__ f2,
                                              const float* __restrict__ W) {
    int br = blockIdx.y;
    const float* feat = br ? f2 : f1;
    float* h = d_h[br];
    const int* dout = d_degout[br];
    int base = blockIdx.x * 128;

    __shared__ float As[128 * 36];   // 128 rows x 32 k, stride 36 (conflict-free frag loads)
    __shared__ float Bs[32 * 136];   // 32 k x 128 n, stride 136
    __shared__ float ssc[128];

    int tid = threadIdx.x, lane = tid & 31, warp = tid >> 5;
    if (tid < 128) {
        int row = base + tid;
        int d = (row < MN) ? dout[row] : 1;
        ssc[tid] = rsqrtf((float)(d > 1 ? d : 1));
    }

    float4 c[16];
#pragma unroll
    for (int j = 0; j < 16; j++) c[j] = make_float4(0.f, 0.f, 0.f, 0.f);
    int g = lane >> 2, tq = lane & 3;
    int wrow = warp * 16;

    for (int kc = 0; kc < 4; kc++) {
        int k0 = kc * 32;
        __syncthreads();
        // fill As (scaled + tf32-rounded)
        for (int idx = tid; idx < 128 * 8; idx += 256) {
            int r = idx >> 3, q = idx & 7;
            int row = base + r;
            float4 v = make_float4(0.f, 0.f, 0.f, 0.f);
            if (row < MN) v = *(const float4*)&feat[(size_t)row * FD + k0 + q * 4];
            float s = ssc[r];
            float* p = &As[r * 36 + q * 4];
            p[0] = f2tf32(v.x * s); p[1] = f2tf32(v.y * s);
            p[2] = f2tf32(v.z * s); p[3] = f2tf32(v.w * s);
        }
        // fill Bs
        for (int idx = tid; idx < 32 * 32; idx += 256) {
            int r = idx >> 5, q = idx & 31;
            float4 v = *(const float4*)&W[(size_t)(k0 + r) * FD + q * 4];
            float* p = &Bs[r * 136 + q * 4];
            p[0] = f2tf32(v.x); p[1] = f2tf32(v.y);
            p[2] = f2tf32(v.z); p[3] = f2tf32(v.w);
        }
        __syncthreads();
#pragma unroll
        for (int ks = 0; ks < 4; ks++) {
            int kk = ks * 8;
            float a0 = As[(wrow + g) * 36 + kk + tq];
            float a1 = As[(wrow + g + 8) * 36 + kk + tq];
            float a2 = As[(wrow + g) * 36 + kk + tq + 4];
            float a3 = As[(wrow + g + 8) * 36 + kk + tq + 4];
#pragma unroll
            for (int j = 0; j < 16; j++) {
                float b0 = Bs[(kk + tq) * 136 + j * 8 + g];
                float b1 = Bs[(kk + tq + 4) * 136 + j * 8 + g];
                asm volatile(
                    "mma.sync.aligned.m16n8k8.row.col.f32.tf32.tf32.f32 "
                    "{%0,%1,%2,%3},{%4,%5,%6,%7},{%8,%9},{%0,%1,%2,%3};"
                    : "+f"(c[j].x), "+f"(c[j].y), "+f"(c[j].z), "+f"(c[j].w)
                    : "r"(__float_as_uint(a0)), "r"(__float_as_uint(a1)),
                      "r"(__float_as_uint(a2)), "r"(__float_as_uint(a3)),
                      "r"(__float_as_uint(b0)), "r"(__float_as_uint(b1)));
            }
        }
    }
    int r0 = base + wrow + g, r1 = r0 + 8;
#pragma unroll
    for (int j = 0; j < 16; j++) {
        int col = j * 8 + tq * 2;
        if (r0 < MN) *(float2*)&h[(size_t)r0 * FD + col] = make_float2(c[j].x, c[j].y);
        if (r1 < MN) *(float2*)&h[(size_t)r1 * FD + col] = make_float2(c[j].z, c[j].w);
    }
}

// ---------------- K5: CSR gather-aggregate + scale + bias + L2norm + sigmoid + pooled ----------------
__global__ void __launch_bounds__(512) k_agg(const float* __restrict__ bvec,
                                             const int* __restrict__ g1,
                                             const int* __restrict__ g2) {
    int br = blockIdx.y;
    const int* gid = br ? g2 : g1;
    const float4* hp = (const float4*)d_h[br];
    const int* rp = d_rowptr[br];
    const int* cs = d_csrsrc[br];
    float* hg = d_hg[br];

    __shared__ float nv[16 * 128];
    __shared__ int sgid[16];

    int tid = threadIdx.x, lane = tid & 31, warp = tid >> 5;
    int node = blockIdx.x * 16 + warp;
    float ax = 0.f, ay = 0.f, az = 0.f, aw = 0.f;

    if (node < MN) {
        int rs = rp[node], re = rp[node + 1];
        int deg = re - rs;
        for (int i = rs; i < re; i++) {
            int s = cs[i];
            float4 v = hp[(size_t)s * 32 + lane];
            ax += v.x; ay += v.y; az += v.z; aw += v.w;
        }
        float sc = rsqrtf((float)(deg > 1 ? deg : 1));
        float4 bb = ((const float4*)bvec)[lane];
        ax = ax * sc + bb.x; ay = ay * sc + bb.y;
        az = az * sc + bb.z; aw = aw * sc + bb.w;
        float ss = ax * ax + ay * ay + az * az + aw * aw;
#pragma unroll
        for (int o = 16; o; o >>= 1) ss += __shfl_xor_sync(0xffffffffu, ss, o);
        float inv = 1.0f / fmaxf(sqrtf(ss), 1e-12f);
        ax = 1.0f / (1.0f + __expf(-ax * inv));
        ay = 1.0f / (1.0f + __expf(-ay * inv));
        az = 1.0f / (1.0f + __expf(-az * inv));
        aw = 1.0f / (1.0f + __expf(-aw * inv));
        if (lane == 0) sgid[warp] = gid[node];
    } else {
        if (lane == 0) sgid[warp] = -1;
    }
    *(float4*)&nv[warp * 128 + lane * 4] = make_float4(ax, ay, az, aw);
    __syncthreads();

    // gid is sorted -> runs are contiguous; one atomic per (run, column) per CTA
    if (tid < 128) {
        int c = tid;
        float acc = 0.f;
        int cur = sgid[0];
#pragma unroll
        for (int i = 0; i < 16; i++) {
            int gg = sgid[i];
            float v = nv[i * 128 + c];
            if (gg != cur) {
                if (cur >= 0) atomicAdd(&hg[cur * 128 + c], acc);
                acc = 0.f;
                cur = gg;
            }
            acc += v;
        }
        if (cur >= 0) atomicAdd(&hg[cur * 128 + c], acc);
    }
}

// ---------------- K6: class projection + pairwise distance ----------------
__global__ void k_final(const float* __restrict__ Wc, const float* __restrict__ bc,
                        float* __restrict__ out) {
    int gph = blockIdx.x, j = threadIdx.x;
    float l[2];
#pragma unroll
    for (int br = 0; br < 2; br++) {
        const float* hgp = &d_hg[br][gph * 128];
        float s = 0.f;
        for (int k = 0; k < 128; k++) s += hgp[k] * Wc[k * NC + j];
        float invc = 1.0f / fmaxf((float)d_gcnt[br][gph], 1.0f);
        l[br] = s * invc + bc[j];
    }
    float dff = l[0] - l[1] + 1e-6f;
    float sq = dff * dff;
#pragma unroll
    for (int o = 16; o; o >>= 1) sq += __shfl_xor_sync(0xffffffffu, sq, o);
    __shared__ float red[2];
    if ((j & 31) == 0) red[j >> 5] = sq;
    __syncthreads();
    if (j == 0) out[gph] = sqrtf(red[0] + red[1]);
}

// ---------------- launch ----------------
extern "C" void kernel_launch(void* const* d_in, const int* in_sizes, int n_in,
                              void* d_out, int out_size) {
    const float* feat1 = (const float*)d_in[0];
    const float* feat2 = (const float*)d_in[1];
    const int* src1 = (const int*)d_in[2];
    const int* dst1 = (const int*)d_in[3];
    const int* gid1 = (const int*)d_in[4];
    const int* src2 = (const int*)d_in[5];
    const int* dst2 = (const int*)d_in[6];
    const int* gid2 = (const int*)d_in[7];
    const float* W  = (const float*)d_in[8];
    const float* b  = (const float*)d_in[9];
    const float* Wc = (const float*)d_in[10];
    const float* bc = (const float*)d_in[11];
    float* out = (float*)d_out;

    k_zero<<<(MN + 511) / 512, 512>>>();
    k_hist<<<dim3((NE + 511) / 512, 2), 512>>>(src1, dst1, src2, dst2);
    k_gcnt<<<dim3((MN + 511) / 512, 2), 512>>>(gid1, gid2);
    k_scan<<<2, 1024>>>();
    k_scatter<<<dim3((NE + 511) / 512, 2), 512>>>(src1, dst1, src2, dst2);
    k_gemm<<<dim3((MN + 127) / 128, 2), 256>>>(feat1, feat2, W);
    k_agg<<<dim3((MN + 15) / 16, 2), 512>>>(b, gid1, gid2);
    k_final<<<NG, 64>>>(Wc, bc, out);
}

// round 3
// speedup vs baseline: 1.1854x; 1.1854x over previous
#include <cuda_runtime.h>
#include <cuda_bf16.h>

#define MN 100000
#define NE 1600000
#define NG 128
#define FD 128
#define NC 64

#define SCAN_BS 512
#define SCAN_CH 2048
#define SCAN_NB ((MN + SCAN_CH - 1) / SCAN_CH)   // 49
#define SCAN_NW (SCAN_BS / 32)                   // 16

// ---------------- device scratch (no runtime allocation allowed) ----------------
__device__ __nv_bfloat16 d_h[2][(size_t)MN * FD];  // projected node features (bf16)
__device__ int   d_degout[2][MN];
__device__ int   d_cursor[2][MN];           // dst histogram -> scatter cursors
__device__ int   d_rowptr[2][MN + 1];
__device__ int   d_csrsrc[2][NE];
__device__ float d_hg[2][NG * FD];          // graph pools
__device__ int   d_gcnt[2][NG];
__device__ int   d_bsum[2][SCAN_NB];
__device__ int   d_boff[2][SCAN_NB];

__device__ __forceinline__ float f2tf32(float x) {
    unsigned u;
    asm("cvt.rna.tf32.f32 %0, %1;" : "=r"(u) : "f"(x));
    return __uint_as_float(u);
}

// ---------------- K0: zero scratch ----------------
__global__ void k_zero() {
    int i = blockIdx.x * blockDim.x + threadIdx.x;
    if (i < MN) {
        d_degout[0][i] = 0; d_degout[1][i] = 0;
        d_cursor[0][i] = 0; d_cursor[1][i] = 0;
    }
    if (i < NG * FD) { d_hg[0][i] = 0.f; d_hg[1][i] = 0.f; }
    if (i < NG) { d_gcnt[0][i] = 0; d_gcnt[1][i] = 0; }
}

// ---------------- K1: degree histograms + per-graph node counts ----------------
__global__ void k_hist(const int* __restrict__ s1, const int* __restrict__ d1,
                       const int* __restrict__ s2, const int* __restrict__ d2,
                       const int* __restrict__ g1, const int* __restrict__ g2) {
    int br = blockIdx.y;
    const int* src = br ? s2 : s1;
    const int* dst = br ? d2 : d1;
    const int* gid = br ? g2 : g1;
    int e = blockIdx.x * blockDim.x + threadIdx.x;
    if (e < NE) {
        atomicAdd(&d_degout[br][src[e]], 1);
        atomicAdd(&d_cursor[br][dst[e]], 1);    // in-degree histogram
    }
    if (e < MN) atomicAdd(&d_gcnt[br][gid[e]], 1);
}

// ---------------- K2a: per-block sums of in-degree histogram ----------------
__global__ void __launch_bounds__(SCAN_BS) k_scan1() {
    int br = blockIdx.y;
    const int* hist = d_cursor[br];
    int base = blockIdx.x * SCAN_CH + threadIdx.x * 4;
    int s = 0;
#pragma unroll
    for (int q = 0; q < 4; q++) {
        int i = base + q;
        if (i < MN) s += hist[i];
    }
    int lane = threadIdx.x & 31, wid = threadIdx.x >> 5;
#pragma unroll
    for (int o = 16; o; o >>= 1) s += __shfl_xor_sync(0xffffffffu, s, o);
    __shared__ int ws[SCAN_NW];
    if (lane == 0) ws[wid] = s;
    __syncthreads();
    if (threadIdx.x == 0) {
        int t = 0;
#pragma unroll
        for (int i = 0; i < SCAN_NW; i++) t += ws[i];
        d_bsum[br][blockIdx.x] = t;
    }
}

// ---------------- K2b: scan the 49 block sums (tiny) ----------------
__global__ void k_scan2() {
    int br = blockIdx.x;
    __shared__ int sv[SCAN_NB];
    if (threadIdx.x < SCAN_NB) sv[threadIdx.x] = d_bsum[br][threadIdx.x];
    __syncthreads();
    if (threadIdx.x == 0) {
        int acc = 0;
        for (int i = 0; i < SCAN_NB; i++) { int v = sv[i]; sv[i] = acc; acc += v; }
        d_rowptr[br][MN] = acc;
    }
    __syncthreads();
    if (threadIdx.x < SCAN_NB) d_boff[br][threadIdx.x] = sv[threadIdx.x];
}

// ---------------- K2c: local exclusive scan + block offset ----------------
__global__ void __launch_bounds__(SCAN_BS) k_scan3() {
    int br = blockIdx.y;
    int* hist = d_cursor[br];
    int* rp = d_rowptr[br];
    int base = blockIdx.x * SCAN_CH + threadIdx.x * 4;
    int v[4];
#pragma unroll
    for (int q = 0; q < 4; q++) {
        int i = base + q;
        v[q] = (i < MN) ? hist[i] : 0;
    }
    int tsum = v[0] + v[1] + v[2] + v[3];
    int lane = threadIdx.x & 31, wid = threadIdx.x >> 5;
    int incl = tsum;
#pragma unroll
    for (int o = 1; o < 32; o <<= 1) {
        int t = __shfl_up_sync(0xffffffffu, incl, o);
        if (lane >= o) incl += t;
    }
    __shared__ int ws[SCAN_NW];
    if (lane == 31) ws[wid] = incl;
    __syncthreads();
    // ALL 32 lanes of warp 0 participate in the shfl (full mask legal);
    // lanes >= SCAN_NW carry zeros and their result is never read.
    if (wid == 0) {
        int s = (lane < SCAN_NW) ? ws[lane] : 0;
        int si = s;
#pragma unroll
        for (int o = 1; o < 32; o <<= 1) {
            int t = __shfl_up_sync(0xffffffffu, si, o);
            if (lane >= o) si += t;
        }
        if (lane < SCAN_NW) ws[lane] = si - s;
    }
    __syncthreads();
    int e = d_boff[br][blockIdx.x] + ws[wid] + incl - tsum;
#pragma unroll
    for (int q = 0; q < 4; q++) {
        int i = base + q;
        if (i < MN) { rp[i] = e; hist[i] = e; }   // hist becomes scatter cursor
        e += v[q];
    }
}

// ---------------- K3: scatter edges into dst-CSR ----------------
__global__ void k_scatter(const int* __restrict__ s1, const int* __restrict__ d1,
                          const int* __restrict__ s2, const int* __restrict__ d2) {
    int br = blockIdx.y;
    const int* src = br ? s2 : s1;
    const int* dst = br ? d2 : d1;
    int e = blockIdx.x * blockDim.x + threadIdx.x;
    if (e < NE) {
        int pos = atomicAdd(&d_cursor[br][dst[e]], 1);
        d_csrsrc[br][pos] = src[e];
    }
}

// ---------------- K4: h = diag(degout^-1/2) * feat @ W  (tf32 mma, bf16 out) ----------------
__global__ void __launch_bounds__(256) k_gemm(const float* __restrict__ f1,
                                              const float* __restrict__ f2,
                                              const float* __restrict__ W) {
    int br = blockIdx.y;
    const float* feat = br ? f2 : f1;
    __nv_bfloat16* h = d_h[br];
    const int* dout = d_degout[br];
    int base = blockIdx.x * 128;

    __shared__ float As[128 * 36];
    __shared__ float Bs[32 * 136];
    __shared__ float ssc[128];

    int tid = threadIdx.x, lane = tid & 31, warp = tid >> 5;
    if (tid < 128) {
        int row = base + tid;
        int d = (row < MN) ? dout[row] : 1;
        ssc[tid] = rsqrtf((float)(d > 1 ? d : 1));
    }

    float4 c[16];
#pragma unroll
    for (int j = 0; j < 16; j++) c[j] = make_float4(0.f, 0.f, 0.f, 0.f);
    int g = lane >> 2, tq = lane & 3;
    int wrow = warp * 16;

    for (int kc = 0; kc < 4; kc++) {
        int k0 = kc * 32;
        __syncthreads();
        for (int idx = tid; idx < 128 * 8; idx += 256) {
            int r = idx >> 3, q = idx & 7;
            int row = base + r;
            float4 v = make_float4(0.f, 0.f, 0.f, 0.f);
            if (row < MN) v = *(const float4*)&feat[(size_t)row * FD + k0 + q * 4];
            float s = ssc[r];
            float* p = &As[r * 36 + q * 4];
            p[0] = f2tf32(v.x * s); p[1] = f2tf32(v.y * s);
            p[2] = f2tf32(v.z * s); p[3] = f2tf32(v.w * s);
        }
        for (int idx = tid; idx < 32 * 32; idx += 256) {
            int r = idx >> 5, q = idx & 31;
            float4 v = *(const float4*)&W[(size_t)(k0 + r) * FD + q * 4];
            float* p = &Bs[r * 136 + q * 4];
            p[0] = f2tf32(v.x); p[1] = f2tf32(v.y);
            p[2] = f2tf32(v.z); p[3] = f2tf32(v.w);
        }
        __syncthreads();
#pragma unroll
        for (int ks = 0; ks < 4; ks++) {
            int kk = ks * 8;
            float a0 = As[(wrow + g) * 36 + kk + tq];
            float a1 = As[(wrow + g + 8) * 36 + kk + tq];
            float a2 = As[(wrow + g) * 36 + kk + tq + 4];
            float a3 = As[(wrow + g + 8) * 36 + kk + tq + 4];
#pragma unroll
            for (int j = 0; j < 16; j++) {
                float b0 = Bs[(kk + tq) * 136 + j * 8 + g];
                float b1 = Bs[(kk + tq + 4) * 136 + j * 8 + g];
                asm volatile(
                    "mma.sync.aligned.m16n8k8.row.col.f32.tf32.tf32.f32 "
                    "{%0,%1,%2,%3},{%4,%5,%6,%7},{%8,%9},{%0,%1,%2,%3};"
                    : "+f"(c[j].x), "+f"(c[j].y), "+f"(c[j].z), "+f"(c[j].w)
                    : "r"(__float_as_uint(a0)), "r"(__float_as_uint(a1)),
                      "r"(__float_as_uint(a2)), "r"(__float_as_uint(a3)),
                      "r"(__float_as_uint(b0)), "r"(__float_as_uint(b1)));
            }
        }
    }
    int r0 = base + wrow + g, r1 = r0 + 8;
#pragma unroll
    for (int j = 0; j < 16; j++) {
        int col = j * 8 + tq * 2;
        if (r0 < MN)
            *(__nv_bfloat162*)&h[(size_t)r0 * FD + col] = __floats2bfloat162_rn(c[j].x, c[j].y);
        if (r1 < MN)
            *(__nv_bfloat162*)&h[(size_t)r1 * FD + col] = __floats2bfloat162_rn(c[j].z, c[j].w);
    }
}

// ---------------- K5: CSR gather-aggregate + scale + bias + L2norm + sigmoid + pool ----------------
__global__ void __launch_bounds__(512) k_agg(const float* __restrict__ bvec,
                                             const int* __restrict__ g1,
                                             const int* __restrict__ g2) {
    int br = blockIdx.y;
    const int* gid = br ? g2 : g1;
    const uint2* hp = (const uint2*)d_h[br];      // 32 x 8B per 128-bf16 row
    const int* rp = d_rowptr[br];
    const int* cs = d_csrsrc[br];
    float* hg = d_hg[br];

    __shared__ float nv[16 * 128];
    __shared__ int sgid[16];

    int tid = threadIdx.x, lane = tid & 31, warp = tid >> 5;
    int node = blockIdx.x * 16 + warp;
    float ax = 0.f, ay = 0.f, az = 0.f, aw = 0.f;

    if (node < MN) {
        int rs = rp[node], re = rp[node + 1];
        int deg = re - rs;
#pragma unroll 2
        for (int i = rs; i < re; i++) {
            int s = cs[i];
            uint2 u = hp[(size_t)s * 32 + lane];
            float2 f0 = __bfloat1622float2(*(__nv_bfloat162*)&u.x);
            float2 f1 = __bfloat1622float2(*(__nv_bfloat162*)&u.y);
            ax += f0.x; ay += f0.y; az += f1.x; aw += f1.y;
        }
        float sc = rsqrtf((float)(deg > 1 ? deg : 1));
        float4 bb = ((const float4*)bvec)[lane];
        ax = ax * sc + bb.x; ay = ay * sc + bb.y;
        az = az * sc + bb.z; aw = aw * sc + bb.w;
        float ss = ax * ax + ay * ay + az * az + aw * aw;
#pragma unroll
        for (int o = 16; o; o >>= 1) ss += __shfl_xor_sync(0xffffffffu, ss, o);
        float inv = 1.0f / fmaxf(sqrtf(ss), 1e-12f);
        ax = 1.0f / (1.0f + __expf(-ax * inv));
        ay = 1.0f / (1.0f + __expf(-ay * inv));
        az = 1.0f / (1.0f + __expf(-az * inv));
        aw = 1.0f / (1.0f + __expf(-aw * inv));
        if (lane == 0) sgid[warp] = gid[node];
    } else {
        if (lane == 0) sgid[warp] = -1;
    }
    *(float4*)&nv[warp * 128 + lane * 4] = make_float4(ax, ay, az, aw);
    __syncthreads();

    // gid sorted -> contiguous runs; one global atomic per (run, column) per CTA
    if (tid < 128) {
        int c = tid;
        float acc = 0.f;
        int cur = sgid[0];
#pragma unroll
        for (int i = 0; i < 16; i++) {
            int gg = sgid[i];
            float v = nv[i * 128 + c];
            if (gg != cur) {
                if (cur >= 0) atomicAdd(&hg[cur * 128 + c], acc);
                acc = 0.f;
                cur = gg;
            }
            acc += v;
        }
        if (cur >= 0) atomicAdd(&hg[cur * 128 + c], acc);
    }
}

// ---------------- K6: class projection + pairwise distance ----------------
__global__ void k_final(const float* __restrict__ Wc, const float* __restrict__ bc,
                        float* __restrict__ out) {
    int gph = blockIdx.x, j = threadIdx.x;
    float l[2];
#pragma unroll
    for (int br = 0; br < 2; br++) {
        const float* hgp = &d_hg[br][gph * 128];
        float s = 0.f;
        for (int k = 0; k < 128; k++) s += hgp[k] * Wc[k * NC + j];
        float invc = 1.0f / fmaxf((float)d_gcnt[br][gph], 1.0f);
        l[br] = s * invc + bc[j];
    }
    float dff = l[0] - l[1] + 1e-6f;
    float sq = dff * dff;
#pragma unroll
    for (int o = 16; o; o >>= 1) sq += __shfl_xor_sync(0xffffffffu, sq, o);
    __shared__ float red[2];
    if ((j & 31) == 0) red[j >> 5] = sq;
    __syncthreads();
    if (j == 0) out[gph] = sqrtf(red[0] + red[1]);
}

// ---------------- launch ----------------
extern "C" void kernel_launch(void* const* d_in, const int* in_sizes, int n_in,
                              void* d_out, int out_size) {
    const float* feat1 = (const float*)d_in[0];
    const float* feat2 = (const float*)d_in[1];
    const int* src1 = (const int*)d_in[2];
    const int* dst1 = (const int*)d_in[3];
    const int* gid1 = (const int*)d_in[4];
    const int* src2 = (const int*)d_in[5];
    const int* dst2 = (const int*)d_in[6];
    const int* gid2 = (const int*)d_in[7];
    const float* W  = (const float*)d_in[8];
    const float* b  = (const float*)d_in[9];
    const float* Wc = (const float*)d_in[10];
    const float* bc = (const float*)d_in[11];
    float* out = (float*)d_out;

    k_zero<<<(MN + 511) / 512, 512>>>();
    k_hist<<<dim3((NE + 511) / 512, 2), 512>>>(src1, dst1, src2, dst2, gid1, gid2);
    k_scan1<<<dim3(SCAN_NB, 2), SCAN_BS>>>();
    k_scan2<<<2, 64>>>();
    k_scan3<<<dim3(SCAN_NB, 2), SCAN_BS>>>();
    k_scatter<<<dim3((NE + 511) / 512, 2), 512>>>(src1, dst1, src2, dst2);
    k_gemm<<<dim3((MN + 127) / 128, 2), 256>>>(feat1, feat2, W);
    k_agg<<<dim3((MN + 15) / 16, 2), 512>>>(b, gid1, gid2);
    k_final<<<NG, 64>>>(Wc, bc, out);
}